// round 9
// baseline (speedup 1.0000x reference)
#include <cuda_runtime.h>

#define NB     256
#define NQ     1000
#define NC     81
#define QCN    81000
#define TOPK   100
#define CAP    8192          // global candidate capacity per batch
#define CAPF   4096          // fallback shared capacity (kernel C)
#define NT     256           // merged-kernel block size
#define NTC    512
#define QPB    40
#define SPLITB 25
#define NBLKA  NB
#define NBLKB  (NB * SPLITB)
#define NBINA  4096
#define NBINC  4096
#define WLO    110           // sample suffix floor -> >=110 survivors guaranteed
#define CPT    16            // candidates per thread (C): 512*16 = 8192

// ---- global scratch (no allocs allowed; zero-initialized at load) ------
__device__ float               g_w1[NB * NQ];
__device__ float               g_w2[NB * NQ];
__device__ float               g_lthr[NB * NQ];
__device__ float               g_thr[NB];
__device__ unsigned            g_thrbits[NB];
__device__ unsigned long long  g_cand[NB * CAP];
__device__ int                 g_cnt[NB];
__device__ int                 g_ready[NB];

__device__ __forceinline__ float sigf(float x) {
    return __fdividef(1.0f, 1.0f + __expf(-x));
}

__device__ __forceinline__ void pushg(int b, unsigned long long key) {
    unsigned m = __activemask();
    int lane   = threadIdx.x & 31;
    int leader = __ffs(m) - 1;
    int rank   = __popc(m & ((1u << lane) - 1u));
    int base   = 0;
    if (lane == leader) base = atomicAdd(&g_cnt[b], __popc(m));
    base = __shfl_sync(m, base, leader);
    int pos = base + rank;
    if (pos < CAP) g_cand[b * CAP + pos] = key;  // overflow counts -> fallback
}

__device__ __forceinline__ void pushs(unsigned long long key,
                                      unsigned long long* cand, int* cnt, int cap) {
    unsigned m = __activemask();
    int lane   = threadIdx.x & 31;
    int leader = __ffs(m) - 1;
    int rank   = __popc(m & ((1u << lane) - 1u));
    int base   = 0;
    if (lane == leader) base = atomicAdd(cnt, __popc(m));
    base = __shfl_sync(m, base, leader);
    int pos = base + rank;
    if (pos < cap) cand[pos] = key;
}

__device__ __forceinline__ float logit_thr(float te, float w1) {
    float r = __fdividef(te, w1);
    if (r >= 0.999999f) return __int_as_float(0x7f800000);  // +inf: none pass
    float lt = __logf(r) - __logf(1.0f - r) - 1e-3f;        // sigmoid^-1 with slack
    return fmaxf(lt, -20.0f);
}

// ============ Kernel AB: threshold producers + scan consumers ============
__global__ __launch_bounds__(NT)
void kernelAB(const float* __restrict__ logits,
              const float* __restrict__ obj,
              const float* __restrict__ unk)
{
    __shared__ float s_w1[NQ];            // A: per-query weights / B: unused
    __shared__ int   s_hist[NBINA];       // 16 KB (A only)
    __shared__ int   s_wsum[NT / 32];
    __shared__ int   s_out[2];
    __shared__ float s_lt[QPB];           // B tables
    __shared__ float s_w1t[QPB];

    const int bid  = blockIdx.x;
    const int tid  = threadIdx.x;
    const int lane = tid & 31;
    const int warp = tid >> 5;

    if (bid < NBLKA) {
        // ================= A role: one block per batch ===================
        const int b = bid;
        const float* lg = logits + (size_t)b * QCN;

        for (int q = tid; q < NQ; q += NT) {
            float w  = __expf(-obj[b * NQ + q]);
            float su = sigf(unk[b * NQ + q]);
            float w1 = w * (1.0f - su);
            s_w1[q] = w1;
            g_w1[b * NQ + q] = w1;
            g_w2[b * NQ + q] = w * su;
        }
        for (int i = tid; i < NBINA; i += NT) s_hist[i] = 0;
        __syncthreads();

        // 4000 samples (every query x classes 0..3), two passes of 8/thread
        for (int half = 0; half < 2; half++) {
            float raw[8]; int sq[8]; bool ok[8];
#pragma unroll
            for (int k = 0; k < 8; k++) {
                int s = (half * 8 + k) * NT + tid;
                int q = s >> 2, c = s & 3;
                sq[k] = q;
                ok[k] = (q < NQ);
                raw[k] = ok[k] ? __ldg(&lg[q * NC + c]) : 0.0f;
            }
#pragma unroll
            for (int k = 0; k < 8; k++) {
                if (ok[k]) {
                    float v = s_w1[sq[k]] * sigf(raw[k]);
                    unsigned idx = __float_as_uint(v) >> 19;
                    if (idx > NBINA - 1) idx = NBINA - 1;
                    atomicAdd(&s_hist[idx], 1);
                }
            }
        }
        __syncthreads();

        // suffix-crossing: largest bin with suffix count >= WLO (16 bins/thread)
        int cs = 0;
        const int t16 = tid * 16;
#pragma unroll
        for (int k = 0; k < 16; k++) cs += s_hist[t16 + k];
        int suf = cs;
#pragma unroll
        for (int off = 1; off < 32; off <<= 1) {
            int v = __shfl_down_sync(0xffffffffu, suf, off);
            if (lane + off < 32) suf += v;
        }
        if (lane == 0) s_wsum[warp] = suf;
        __syncthreads();
        int wsuf = 0;
        for (int w2i = warp + 1; w2i < NT / 32; w2i++) wsuf += s_wsum[w2i];
        int sufExcl = wsuf + (suf - cs);
        if (sufExcl < WLO && sufExcl + cs >= WLO) {
            int run = sufExcl;
#pragma unroll
            for (int k = 15; k >= 0; k--) {
                run += s_hist[t16 + k];
                if (run >= WLO) { s_out[0] = t16 + k; break; }
            }
        }
        __syncthreads();

        unsigned thrbits = (unsigned)s_out[0] << 19;
        float thrf = __uint_as_float(thrbits);
        if (tid == 0) { g_thr[b] = thrf; g_thrbits[b] = thrbits; }
        float te = thrf * 0.9999f;

        for (int q = tid; q < NQ; q += NT)
            g_lthr[b * NQ + q] = logit_thr(te, s_w1[q]);

        // publish (release)
        __threadfence();
        __syncthreads();
        if (tid == 0) atomicExch(&g_ready[b], 1);

        // class-80 specials (only C consumes; kernel boundary orders them)
        for (int q = tid; q < NQ; q += NT) {
            float w2 = g_w2[b * NQ + q];
            if (w2 >= te) {
                unsigned i = (unsigned)(q * NC + 80);
                pushg(b, ((unsigned long long)__float_as_uint(w2) << 32) | (~i));
            }
        }
    } else {
        // ================= B role: 25 chunk-blocks per batch =============
        const int r  = bid - NBLKA;
        const int b  = r & (NB - 1);
        const int qb = (r >> 8) * QPB;
        const float* lg = logits + (size_t)b * QCN;

        // prefetch logit rows BEFORE waiting on the threshold
        float v0[5], v1[5];
        int   qv[5];
#pragma unroll
        for (int j = 0; j < 5; j++) {
            int q = qb + warp + 8 * j;
            qv[j] = q;
            const float* base = lg + q * NC;
            v0[j] = base[lane];                              // classes 0..31
            v1[j] = (lane < 28) ? base[32 + lane] : -1e30f;  // classes 32..59
        }

        // wait for this batch's threshold
        if (tid == 0) {
            while (((volatile int*)g_ready)[b] == 0) __nanosleep(128);
        }
        __syncthreads();
        __threadfence();   // acquire: order table loads after flag

        if (tid < QPB) {
            s_lt[tid]  = g_lthr[b * NQ + qb + tid];
            s_w1t[tid] = g_w1[b * NQ + qb + tid];
        }
        __syncthreads();

        float lt[5], w1[5];
#pragma unroll
        for (int j = 0; j < 5; j++) {
            int li = warp + 8 * j;
            lt[j] = s_lt[li];
            w1[j] = s_w1t[li];
        }
#pragma unroll
        for (int j = 0; j < 5; j++) {
            if (v0[j] >= lt[j]) {
                float p = w1[j] * sigf(v0[j]);
                unsigned i = (unsigned)(qv[j] * NC + lane);
                pushg(b, ((unsigned long long)__float_as_uint(p) << 32) | (~i));
            }
            if (v1[j] >= lt[j]) {
                float p = w1[j] * sigf(v1[j]);
                unsigned i = (unsigned)(qv[j] * NC + 32 + lane);
                pushg(b, ((unsigned long long)__float_as_uint(p) << 32) | (~i));
            }
        }
    }
}

// ======================= Kernel C: refine + small sort + emit ============
__global__ __launch_bounds__(NTC)
void kernelC(const float* __restrict__ logits,
             const float* __restrict__ boxes,
             const float* __restrict__ tsizes,
             float* __restrict__ out)
{
    __shared__ unsigned long long s_cand[CAPF];   // 32 KB; upper half aliased as hist
    __shared__ float s_w1[NQ], s_w2[NQ], s_lthr[NQ];
    __shared__ int   s_wsum[NTC / 32];
    __shared__ int   s_out[2];
    __shared__ int   s_cnt;

    int* s_hist = (int*)(s_cand + 2048);          // 4096 ints in upper half

    const int b   = blockIdx.x;
    const int tid = threadIdx.x;
    const float* lg = logits + (size_t)b * QCN;

    int n = g_cnt[b];
    __syncthreads();
    if (tid == 0) { g_cnt[b] = 0; g_ready[b] = 0; }   // reset for next replay
    int n_sort;

    if (n >= TOPK && n <= CAP) {
        // ---- normal path ------------------------------------------------
        unsigned long long kr[CPT];
#pragma unroll
        for (int k = 0; k < CPT; k++) {
            int t = tid + k * NTC;
            kr[k] = (t < n) ? g_cand[b * CAP + t] : 0ULL;   // predicated off past n
            if (k * NTC >= n) break;                        // early exit: skip dead tail
        }
#pragma unroll
        for (int k = 0; k < CPT; k++)
            if (tid + k * NTC >= n) kr[k] = 0ULL;
#pragma unroll
        for (int k = 0; k < NBINC / NTC; k++) s_hist[k * NTC + tid] = 0;
        __syncthreads();

        unsigned base = g_thrbits[b] >> 16;       // fine-bin base
#pragma unroll
        for (int k = 0; k < CPT; k++) {
            if (tid + k * NTC < n) {
                int idx = (int)((unsigned)(kr[k] >> 32) >> 16) - (int)base;
                idx = (idx < 0) ? 0 : ((idx > NBINC - 1) ? NBINC - 1 : idx);
                atomicAdd(&s_hist[idx], 1);
            }
        }
        __syncthreads();

        int binv[8], cs = 0;
        int t8 = tid * 8;
#pragma unroll
        for (int k = 0; k < 8; k++) { binv[k] = s_hist[t8 + k]; cs += binv[k]; }
        {
            int lane = tid & 31, w = tid >> 5;
            int suf = cs;
#pragma unroll
            for (int off = 1; off < 32; off <<= 1) {
                int v = __shfl_down_sync(0xffffffffu, suf, off);
                if (lane + off < 32) suf += v;
            }
            if (lane == 0) s_wsum[w] = suf;
            __syncthreads();
            int wsuf = 0;
            for (int w2 = w + 1; w2 < NTC / 32; w2++) wsuf += s_wsum[w2];
            int sufExcl = wsuf + (suf - cs);
            if (sufExcl < TOPK && sufExcl + cs >= TOPK) {
                int run = sufExcl;
#pragma unroll
                for (int k = 7; k >= 0; k--) {
                    run += binv[k];
                    if (run >= TOPK) { s_out[0] = t8 + k; s_out[1] = run; break; }
                }
            }
            __syncthreads();
        }

        int bin2 = s_out[0];
        int cum  = s_out[1];
        if (cum <= 256) {
            n_sort = (cum <= 128) ? 128 : 256;
            unsigned thr2 = (bin2 == 0) ? 0u : ((base + (unsigned)bin2) << 16);
            if (tid == 0) s_cnt = 0;
            __syncthreads();
#pragma unroll
            for (int k = 0; k < CPT; k++) {
                if (tid + k * NTC < n && (unsigned)(kr[k] >> 32) >= thr2)
                    pushs(kr[k], s_cand, &s_cnt, n_sort);
            }
            __syncthreads();
            for (int t = s_cnt + tid; t < n_sort; t += NTC) s_cand[t] = 0ULL;
            __syncthreads();
        } else {
            // tie pathology: full sort of candidates
            int m = (n < CAPF) ? n : CAPF;
            __syncthreads();
            for (int t = tid; t < CAPF; t += NTC)
                s_cand[t] = (t < m) ? g_cand[b * CAP + t] : 0ULL;
            __syncthreads();
            n_sort = CAPF;
        }
    } else {
        // ---- fallback: bounded rescan with retry (dead in practice) -----
        for (int q = tid; q < NQ; q += NTC) {
            s_w1[q] = g_w1[b * NQ + q];
            s_w2[q] = g_w2[b * NQ + q];
        }
        __syncthreads();
        float curthr = g_thr[b];
        if (curthr <= 0.0f) curthr = 1e-6f;
        for (int attempt = 0; attempt < 12; attempt++) {
            if (n < TOPK) curthr *= 0.25f; else curthr *= 4.0f;
            float te = curthr * 0.9999f;
            for (int q = tid; q < NQ; q += NTC)
                s_lthr[q] = logit_thr(te, s_w1[q]);
            if (tid == 0) s_cnt = 0;
            __syncthreads();
            for (int q = tid; q < NQ; q += NTC) {
                if (s_w2[q] >= te) {
                    unsigned i = (unsigned)(q * NC + 80);
                    pushs(((unsigned long long)__float_as_uint(s_w2[q]) << 32) | (~i),
                          s_cand, &s_cnt, CAPF);
                }
            }
            for (int i = tid; i < QCN; i += NTC) {
                unsigned q = (unsigned)i / NC;
                int c = i - (int)q * NC;
                if (c < 60) {
                    float v = lg[i];
                    if (v >= s_lthr[q]) {
                        float p = s_w1[q] * sigf(v);
                        pushs(((unsigned long long)__float_as_uint(p) << 32) |
                              (~(unsigned)i), s_cand, &s_cnt, CAPF);
                    }
                }
            }
            __syncthreads();
            n = s_cnt;
            if (n >= TOPK && n <= CAPF) break;
            __syncthreads();
        }
        if (n > CAPF) n = CAPF;
        for (int t = n + tid; t < CAPF; t += NTC) s_cand[t] = 0ULL;
        __syncthreads();
        n_sort = CAPF;
    }

    // bitonic ascending sort of n_sort x u64
    for (int k = 2; k <= n_sort; k <<= 1)
        for (int j = k >> 1; j > 0; j >>= 1) {
            for (int t = tid; t < n_sort; t += NTC) {
                int x = t ^ j;
                if (x > t) {
                    unsigned long long a = s_cand[t], bb = s_cand[x];
                    bool up = ((t & k) == 0);
                    if (up ? (a > bb) : (a < bb)) { s_cand[t] = bb; s_cand[x] = a; }
                }
            }
            __syncthreads();
        }

    // emit top-100 (descending from the back)
    if (tid < TOPK) {
        unsigned long long key = s_cand[n_sort - 1 - tid];
        float v    = __uint_as_float((unsigned)(key >> 32));
        unsigned i = ~(unsigned)key;
        if (key == 0ULL) { v = 0.0f; i = 0; }
        unsigned q = i / NC;
        unsigned c = i - q * NC;
        int o = b * TOPK + tid;
        out[o] = v;                               // scores
        out[NB * TOPK + o] = (float)c;            // labels
        const float* bx = boxes + ((size_t)(b * NQ + q)) * 4;
        float cx = bx[0], cy = bx[1], w = bx[2], h = bx[3];
        float ih = tsizes[b * 2 + 0];
        float iw = tsizes[b * 2 + 1];
        float* ob = out + 2 * NB * TOPK + (size_t)o * 4;  // boxes
        ob[0] = (cx - 0.5f * w) * iw;
        ob[1] = (cy - 0.5f * h) * ih;
        ob[2] = (cx + 0.5f * w) * iw;
        ob[3] = (cy + 0.5f * h) * ih;
    }
}

extern "C" void kernel_launch(void* const* d_in, const int* in_sizes, int n_in,
                              void* d_out, int out_size) {
    const float* logits = (const float*)d_in[0];
    const float* obj    = (const float*)d_in[1];
    const float* boxes  = (const float*)d_in[2];
    const float* unk    = (const float*)d_in[3];
    const float* ts     = (const float*)d_in[4];
    float* out = (float*)d_out;

    kernelAB<<<NBLKA + NBLKB, NT>>>(logits, obj, unk);
    kernelC<<<NB, NTC>>>(logits, boxes, ts, out);
}

// round 10
// speedup vs baseline: 1.2080x; 1.2080x over previous
#include <cuda_runtime.h>

#define NB     256
#define NQ     1000
#define NC     81
#define QCN    81000
#define TOPK   100
#define CAP    8192          // global candidate capacity per batch
#define CAPF   2048          // fallback shared capacity (kernel C)
#define NTA    1024
#define NTB    256
#define NTC    512
#define QPB    40
#define SPLITB 25
#define NBINA  4096
#define NBINC  4096
#define WLO    110           // sample suffix floor -> >=110 survivors guaranteed
#define SRTN   256           // survivor capacity for rank-emit path

// ---- global scratch (no allocs allowed; zero-initialized at load) ------
__device__ float               g_w1[NB * NQ];
__device__ float               g_w2[NB * NQ];
__device__ float               g_lthr[NB * NQ];
__device__ float               g_thr[NB];
__device__ unsigned            g_thrbits[NB];
__device__ unsigned long long  g_cand[NB * CAP];
__device__ int                 g_cnt[NB];

__device__ __forceinline__ float sigf(float x) {
    return __fdividef(1.0f, 1.0f + __expf(-x));
}

__device__ __forceinline__ void pushg(int b, unsigned long long key) {
    unsigned m = __activemask();
    int lane   = threadIdx.x & 31;
    int leader = __ffs(m) - 1;
    int rank   = __popc(m & ((1u << lane) - 1u));
    int base   = 0;
    if (lane == leader) base = atomicAdd(&g_cnt[b], __popc(m));
    base = __shfl_sync(m, base, leader);
    int pos = base + rank;
    if (pos < CAP) g_cand[b * CAP + pos] = key;  // overflow counts -> fallback
}

__device__ __forceinline__ void pushs(unsigned long long key,
                                      unsigned long long* cand, int* cnt, int cap) {
    unsigned m = __activemask();
    int lane   = threadIdx.x & 31;
    int leader = __ffs(m) - 1;
    int rank   = __popc(m & ((1u << lane) - 1u));
    int base   = 0;
    if (lane == leader) base = atomicAdd(cnt, __popc(m));
    base = __shfl_sync(m, base, leader);
    int pos = base + rank;
    if (pos < cap) cand[pos] = key;
}

__device__ __forceinline__ float logit_thr(float te, float w1) {
    float r = __fdividef(te, w1);
    if (r >= 0.999999f) return __int_as_float(0x7f800000);  // +inf: none pass
    float lt = __logf(r) - __logf(1.0f - r) - 1e-3f;        // sigmoid^-1 with slack
    return fmaxf(lt, -20.0f);
}

// find largest bin with suffix_cum >= target; result -> s_out[0]=bin, s_out[1]=cum
template<int NT, int BPT>
__device__ __forceinline__ void suffix_find(const int* binv, int cs, int target,
                                            int* s_wsum, int* s_out) {
    const int NW = NT / 32;
    int tid = threadIdx.x, lane = tid & 31, w = tid >> 5;
    int suf = cs;
#pragma unroll
    for (int off = 1; off < 32; off <<= 1) {
        int v = __shfl_down_sync(0xffffffffu, suf, off);
        if (lane + off < 32) suf += v;
    }
    if (lane == 0) s_wsum[w] = suf;
    __syncthreads();
    int wsuf = 0;
    for (int w2 = w + 1; w2 < NW; w2++) wsuf += s_wsum[w2];
    int sufExcl = wsuf + (suf - cs);     // strictly above this thread's bins
    if (sufExcl < target && sufExcl + cs >= target) {
        int run = sufExcl;
#pragma unroll
        for (int k = BPT - 1; k >= 0; k--) {
            run += binv[k];
            if (run >= target) { s_out[0] = tid * BPT + k; s_out[1] = run; break; }
        }
    }
    __syncthreads();
}

// ======================= Kernel A: weights + threshold ===================
__global__ __launch_bounds__(NTA)
void kernelA(const float* __restrict__ logits,
             const float* __restrict__ obj,
             const float* __restrict__ unk)
{
    __shared__ float s_w1[NQ];
    __shared__ int   s_hist[NBINA];
    __shared__ int   s_wsum[NTA / 32];
    __shared__ int   s_out[2];

    const int b   = blockIdx.x;
    const int tid = threadIdx.x;
    const float* lg = logits + (size_t)b * QCN;

    // issue sample loads FIRST (independent of obj/unk)
    float raw[4];
    int   sq[4];
    bool  ok[4];
#pragma unroll
    for (int k = 0; k < 4; k++) {
        int s = k * NTA + tid;
        int q = s >> 2, c = s & 3;
        sq[k] = q;
        ok[k] = (q < NQ);
        raw[k] = ok[k] ? __ldg(&lg[q * NC + c]) : 0.0f;
    }

    if (tid == 0) g_cnt[b] = 0;
#pragma unroll
    for (int k = 0; k < NBINA / NTA; k++) s_hist[k * NTA + tid] = 0;

    float w1v = 0.0f, w2v = 0.0f;
    if (tid < NQ) {
        float w  = __expf(-obj[b * NQ + tid]);
        float su = sigf(unk[b * NQ + tid]);
        w1v = w * (1.0f - su);
        w2v = w * su;
        s_w1[tid] = w1v;
        g_w1[b * NQ + tid] = w1v;
        g_w2[b * NQ + tid] = w2v;
    }
    __syncthreads();

#pragma unroll
    for (int k = 0; k < 4; k++) {
        if (ok[k]) {
            float v = s_w1[sq[k]] * sigf(raw[k]);
            unsigned idx = __float_as_uint(v) >> 19;
            if (idx > NBINA - 1) idx = NBINA - 1;
            atomicAdd(&s_hist[idx], 1);
        }
    }
    __syncthreads();

    int binv[NBINA / NTA], cs = 0;
#pragma unroll
    for (int k = 0; k < NBINA / NTA; k++) {
        binv[k] = s_hist[tid * (NBINA / NTA) + k];
        cs += binv[k];
    }
    suffix_find<NTA, NBINA / NTA>(binv, cs, WLO, s_wsum, s_out);

    unsigned thrbits = (unsigned)s_out[0] << 19;
    float thrf = __uint_as_float(thrbits);
    if (tid == 0) { g_thr[b] = thrf; g_thrbits[b] = thrbits; }
    float te = thrf * 0.9999f;

    if (tid < NQ) {
        g_lthr[b * NQ + tid] = logit_thr(te, w1v);
        if (w2v >= te) {
            unsigned i = (unsigned)(tid * NC + 80);
            pushg(b, ((unsigned long long)__float_as_uint(w2v) << 32) | (~i));
        }
    }
}

// ======================= Kernel B: query-major scan (smem tables) ========
__global__ __launch_bounds__(NTB)
void kernelB(const float* __restrict__ logits)
{
    __shared__ float s_lt[QPB];
    __shared__ float s_w1t[QPB];

    const int b    = blockIdx.y;
    const int qb   = blockIdx.x * QPB;
    const int lane = threadIdx.x & 31;
    const int warp = threadIdx.x >> 5;
    const int tid  = threadIdx.x;
    const float* lg = logits + (size_t)b * QCN;

    if (tid < QPB) {
        s_lt[tid]  = g_lthr[b * NQ + qb + tid];
        s_w1t[tid] = g_w1[b * NQ + qb + tid];
    }
    __syncthreads();

    float v0[5], v1[5], lt[5], w1[5];
    int   qv[5];
#pragma unroll
    for (int j = 0; j < 5; j++) {
        int q = qb + warp + 8 * j;
        qv[j] = q;
        const float* base = lg + q * NC;
        v0[j] = base[lane];                              // classes 0..31
        v1[j] = (lane < 28) ? base[32 + lane] : -1e30f;  // classes 32..59
        int li = warp + 8 * j;
        lt[j] = s_lt[li];                                // LDS broadcast
        w1[j] = s_w1t[li];
    }
#pragma unroll
    for (int j = 0; j < 5; j++) {
        if (v0[j] >= lt[j]) {
            float p = w1[j] * sigf(v0[j]);
            unsigned i = (unsigned)(qv[j] * NC + lane);
            pushg(b, ((unsigned long long)__float_as_uint(p) << 32) | (~i));
        }
        if (v1[j] >= lt[j]) {
            float p = w1[j] * sigf(v1[j]);
            unsigned i = (unsigned)(qv[j] * NC + 32 + lane);
            pushg(b, ((unsigned long long)__float_as_uint(p) << 32) | (~i));
        }
    }
}

// ============ Kernel C: stream-refine + rank-count emit ==================
__global__ __launch_bounds__(NTC)
void kernelC(const float* __restrict__ logits,
             const float* __restrict__ boxes,
             const float* __restrict__ tsizes,
             float* __restrict__ out)
{
    __shared__ unsigned long long s_buf[CAPF];    // 16 KB: hist alias / fallback sort
    __shared__ unsigned long long s_srt[SRTN];    // 2 KB survivors
    __shared__ int   s_wsum[NTC / 32];
    __shared__ int   s_out[2];
    __shared__ int   s_cnt;

    int* s_hist = (int*)s_buf;                    // 4096 ints

    const int b   = blockIdx.x;
    const int tid = threadIdx.x;
    const float* lg = logits + (size_t)b * QCN;

    int n = g_cnt[b];
    int n_sort = 0;

    if (n >= TOPK && n <= CAP) {
        // ---- pass 1: histogram straight from global candidates ----------
        for (int i = tid; i < NBINC; i += NTC) s_hist[i] = 0;
        __syncthreads();
        unsigned base = g_thrbits[b] >> 16;
        for (int t = tid; t < n; t += NTC) {
            unsigned bits = (unsigned)(g_cand[b * CAP + t] >> 32);
            int idx = (int)(bits >> 16) - (int)base;
            idx = (idx < 0) ? 0 : ((idx > NBINC - 1) ? NBINC - 1 : idx);
            atomicAdd(&s_hist[idx], 1);
        }
        __syncthreads();

        int binv[8], cs = 0;
        int t8 = tid * 8;
#pragma unroll
        for (int k = 0; k < 8; k++) { binv[k] = s_hist[t8 + k]; cs += binv[k]; }
        suffix_find<NTC, 8>(binv, cs, TOPK, s_wsum, s_out);

        int bin2 = s_out[0];
        int cum  = s_out[1];
        if (cum <= SRTN) {
            // ---- pass 2: push survivors (L2-hot reload) -----------------
            unsigned thr2 = (bin2 == 0) ? 0u : ((base + (unsigned)bin2) << 16);
            if (tid == 0) s_cnt = 0;
            __syncthreads();
            for (int t = tid; t < n; t += NTC) {
                unsigned long long key = g_cand[b * CAP + t];
                if ((unsigned)(key >> 32) >= thr2)
                    pushs(key, s_srt, &s_cnt, SRTN);
            }
            __syncthreads();
            int m = s_cnt;   // == cum, in [TOPK, SRTN]

            // ---- rank-by-count: no sort, no barriers --------------------
            if (tid < m) {
                unsigned long long my = s_srt[tid];
                int r = 0;
                for (int j = 0; j < m; j++)
                    r += (s_srt[j] > my);        // broadcast LDS
                if (r < TOPK) {
                    float v    = __uint_as_float((unsigned)(my >> 32));
                    unsigned i = ~(unsigned)my;
                    unsigned q = i / NC;
                    unsigned c = i - q * NC;
                    int o = b * TOPK + r;
                    out[o] = v;                               // scores
                    out[NB * TOPK + o] = (float)c;            // labels
                    const float* bx = boxes + ((size_t)(b * NQ + q)) * 4;
                    float cx = bx[0], cy = bx[1], w = bx[2], h = bx[3];
                    float ih = tsizes[b * 2 + 0];
                    float iw = tsizes[b * 2 + 1];
                    float* ob = out + 2 * NB * TOPK + (size_t)o * 4;
                    ob[0] = (cx - 0.5f * w) * iw;
                    ob[1] = (cy - 0.5f * h) * ih;
                    ob[2] = (cx + 0.5f * w) * iw;
                    ob[3] = (cy + 0.5f * h) * ih;
                }
            }
            return;   // normal path done
        }
        // tie pathology: bitonic-sort up to CAPF candidates
        int mm = (n < CAPF) ? n : CAPF;
        __syncthreads();
        for (int t = tid; t < CAPF; t += NTC)
            s_buf[t] = (t < mm) ? g_cand[b * CAP + t] : 0ULL;
        __syncthreads();
        n_sort = CAPF;
    } else {
        // ---- fallback: bounded rescan with retry (dead in practice) -----
        float curthr = g_thr[b];
        if (curthr <= 0.0f) curthr = 1e-6f;
        for (int attempt = 0; attempt < 12; attempt++) {
            if (n < TOPK) curthr *= 0.25f; else curthr *= 4.0f;
            float te = curthr * 0.9999f;
            if (tid == 0) s_cnt = 0;
            __syncthreads();
            for (int i = tid; i < QCN; i += NTC) {
                unsigned q = (unsigned)i / NC;
                int c = i - (int)q * NC;
                float p = -1.0f;
                if (c < 60)       p = g_w1[b * NQ + q] * sigf(lg[i]);
                else if (c == 80) p = g_w2[b * NQ + q];
                if (p >= te)
                    pushs(((unsigned long long)__float_as_uint(p) << 32) |
                          (~(unsigned)i), s_buf, &s_cnt, CAPF);
            }
            __syncthreads();
            n = s_cnt;
            if (n >= TOPK && n <= CAPF) break;
            __syncthreads();
        }
        if (n > CAPF) n = CAPF;
        for (int t = n + tid; t < CAPF; t += NTC) s_buf[t] = 0ULL;
        __syncthreads();
        n_sort = CAPF;
    }

    // ---- bitonic ascending sort (tie/fallback paths only) ---------------
    for (int k = 2; k <= n_sort; k <<= 1)
        for (int j = k >> 1; j > 0; j >>= 1) {
            for (int t = tid; t < n_sort; t += NTC) {
                int x = t ^ j;
                if (x > t) {
                    unsigned long long a = s_buf[t], bb = s_buf[x];
                    bool up = ((t & k) == 0);
                    if (up ? (a > bb) : (a < bb)) { s_buf[t] = bb; s_buf[x] = a; }
                }
            }
            __syncthreads();
        }

    if (tid < TOPK) {
        unsigned long long key = s_buf[n_sort - 1 - tid];
        float v    = __uint_as_float((unsigned)(key >> 32));
        unsigned i = ~(unsigned)key;
        if (key == 0ULL) { v = 0.0f; i = 0; }
        unsigned q = i / NC;
        unsigned c = i - q * NC;
        int o = b * TOPK + tid;
        out[o] = v;
        out[NB * TOPK + o] = (float)c;
        const float* bx = boxes + ((size_t)(b * NQ + q)) * 4;
        float cx = bx[0], cy = bx[1], w = bx[2], h = bx[3];
        float ih = tsizes[b * 2 + 0];
        float iw = tsizes[b * 2 + 1];
        float* ob = out + 2 * NB * TOPK + (size_t)o * 4;
        ob[0] = (cx - 0.5f * w) * iw;
        ob[1] = (cy - 0.5f * h) * ih;
        ob[2] = (cx + 0.5f * w) * iw;
        ob[3] = (cy + 0.5f * h) * ih;
    }
}

extern "C" void kernel_launch(void* const* d_in, const int* in_sizes, int n_in,
                              void* d_out, int out_size) {
    const float* logits = (const float*)d_in[0];
    const float* obj    = (const float*)d_in[1];
    const float* boxes  = (const float*)d_in[2];
    const float* unk    = (const float*)d_in[3];
    const float* ts     = (const float*)d_in[4];
    float* out = (float*)d_out;

    kernelA<<<NB, NTA>>>(logits, obj, unk);
    kernelB<<<dim3(SPLITB, NB), NTB>>>(logits);
    kernelC<<<NB, NTC>>>(logits, boxes, ts, out);
}